// round 14
// baseline (speedup 1.0000x reference)
#include <cuda_runtime.h>
#include <cuda_fp16.h>
#include <cstdint>

#define HID 1024
#define ITR 704
#define NEXP 32
#define TTOK 8192
#define MAXT 64
#define BM 256
#define ABYTES (256*80)             // 20480 per A stage (x3)
#define BBASE  (3*ABYTES)           // 61440
#define BBYTES (32*272)             // 8704 per B stage (x3) : 128 cols fp16 + pad
#define SMEMSZ (BBASE + 3*BBYTES)   // 87552

__device__ int d_te[MAXT], d_tr0[MAXT], d_trs[MAXT], d_nt;
__device__ unsigned short d_xh[(size_t)TTOK * HID];
__device__ unsigned short d_hbuf[(size_t)TTOK * ITR];

__device__ __forceinline__ uint32_t smem_u32(const void* p) {
    uint32_t a;
    asm("{ .reg .u64 t; cvta.to.shared.u64 t, %1; cvt.u32.u64 %0, t; }" : "=r"(a) : "l"(p));
    return a;
}
__device__ __forceinline__ void cp16(uint32_t dst, const void* src) {
    asm volatile("cp.async.ca.shared.global [%0], [%1], 16;" :: "r"(dst), "l"(src));
}
#define CPCOMMIT() asm volatile("cp.async.commit_group;" ::: "memory")
#define CPWAIT1()  asm volatile("cp.async.wait_group 1;" ::: "memory")

#define LDSM4(r, a) \
    asm volatile("ldmatrix.sync.aligned.m8n8.x4.shared.b16 {%0,%1,%2,%3}, [%4];" \
        : "=r"((r)[0]), "=r"((r)[1]), "=r"((r)[2]), "=r"((r)[3]) : "r"(a))
#define LDSM4T(r, a) \
    asm volatile("ldmatrix.sync.aligned.m8n8.x4.trans.shared.b16 {%0,%1,%2,%3}, [%4];" \
        : "=r"((r)[0]), "=r"((r)[1]), "=r"((r)[2]), "=r"((r)[3]) : "r"(a))

__device__ __forceinline__ void mma16(float* c, const uint32_t* a, const uint32_t* b) {
    asm volatile(
        "mma.sync.aligned.m16n8k16.row.col.f32.f16.f16.f32 "
        "{%0,%1,%2,%3},{%4,%5,%6,%7},{%8,%9},{%0,%1,%2,%3};"
        : "+f"(c[0]), "+f"(c[1]), "+f"(c[2]), "+f"(c[3])
        : "r"(a[0]), "r"(a[1]), "r"(a[2]), "r"(a[3]), "r"(b[0]), "r"(b[1]));
}
__device__ __forceinline__ uint32_t h2u(__half2 h) { return *(uint32_t*)&h; }

__global__ void prep_kernel(const float* __restrict__ x, const int* __restrict__ tpe) {
    if (blockIdx.x == 0 && threadIdx.x < 32) {
        const int e = threadIdx.x;
        const int c = tpe[e];
        const int nte = (c + BM - 1) / BM;
        int off = c, tb = nte;
        #pragma unroll
        for (int d = 1; d < 32; d <<= 1) {
            int o2 = __shfl_up_sync(0xffffffffu, off, d);
            int t2 = __shfl_up_sync(0xffffffffu, tb, d);
            if (e >= d) { off += o2; tb += t2; }
        }
        const int row0 = off - c, t0 = tb - nte;
        for (int i = 0; i < nte; i++) {
            d_te[t0 + i]  = e;
            d_tr0[t0 + i] = row0 + i * BM;
            d_trs[t0 + i] = min(BM, c - i * BM);
        }
        if (e == 31) d_nt = tb;
    }
    const size_t i = ((size_t)blockIdx.x * 256 + threadIdx.x) * 8;
    float4 v0 = *(const float4*)(x + i);
    float4 v1 = *(const float4*)(x + i + 4);
    uint4 q;
    q.x = h2u(__floats2half2_rn(v0.x, v0.y));
    q.y = h2u(__floats2half2_rn(v0.z, v0.w));
    q.z = h2u(__floats2half2_rn(v1.x, v1.y));
    q.w = h2u(__floats2half2_rn(v1.z, v1.w));
    *(uint4*)(d_xh + i) = q;
}

template <int G>
__global__ __launch_bounds__(512, 1) void moe_gemm(const float* __restrict__ Bin,
                                                   float* __restrict__ Out) {
    extern __shared__ __align__(16) char sm[];
    const int tile = blockIdx.y;
    if (tile >= d_nt) return;
    constexpr int KT   = (G == 1) ? 32 : 22;
    constexpr int AST  = (G == 1) ? HID : ITR;          // A row stride (halves)
    constexpr int BROW = (G == 1) ? (2 * ITR) : HID;    // B row stride (floats)
    const int e = d_te[tile], row0 = d_tr0[tile], rows = d_trs[tile];
    const int n0 = blockIdx.x * ((G == 1) ? 64 : 128);

    const int tid = threadIdx.x, w = tid >> 5, l = tid & 31;
    const int wm = (w >> 2) * 64;        // 4 M bands of 64
    const int wq = w & 3;                // 4 N quarters
    const uint32_t smb = smem_u32(sm);

    const int mi_max = min(4, max(0, (rows - wm + 15) >> 4));

    const unsigned short* Ah = (G == 1) ? d_xh : d_hbuf;
    const float* Bg = Bin + (size_t)e * ((G == 1) ? (size_t)HID * (2 * ITR)
                                                  : (size_t)ITR * HID);

    // B smem col groups for this warp:
    //  G1: gate cols [wq*16, +16)  and up cols [64 + wq*16, +16)
    //  G2: cols [wq*32, +16) and [wq*32+16, +16)
    const int colA = (G == 1) ? (wq * 16) : (wq * 32);
    const int colB = (G == 1) ? (64 + wq * 16) : (wq * 32 + 16);

    // A staging: one row per 2 threads, 32B (2 cp16) per thread per iter
    const int ar = tid >> 1, ka = (tid & 1) * 16;       // halves
    const size_t ga = (size_t)min(row0 + ar, TTOK - 1) * AST + ka;
    const uint32_t adst = (uint32_t)(ar * 80 + ka * 2);

    // B staging: row kb = tid>>4 (32 rows), 8 fp32 cols at nb
    const int kb = tid >> 4, nb = (tid & 15) * 8;
    size_t boff[2];
    #pragma unroll
    for (int j = 0; j < 2; j++) {
        int nloc = nb + 4 * j;
        int col = (G == 1) ? ((nloc < 64) ? (n0 + nloc) : (ITR + n0 + nloc - 64))
                           : (n0 + nloc);
        boff[j] = (size_t)kb * BROW + col;
    }
    const int bofs = kb * 272 + nb * 2;

    #define CPA(it) do { if ((it) < KT) { \
        const uint32_t _d = smb + (uint32_t)((((it) % 3)) * ABYTES) + adst; \
        const unsigned short* _s = Ah + ga + (size_t)(it) * 32; \
        cp16(_d, _s); \
        cp16(_d + 16, _s + 8); } } while (0)

    float4 bv[2];
    #define LDGB(it) do { if ((it) < KT) { \
        bv[0] = *(const float4*)(Bg + boff[0] + (size_t)(it) * 32 * BROW); \
        bv[1] = *(const float4*)(Bg + boff[1] + (size_t)(it) * 32 * BROW); } } while (0)

    #define STSB(st) do { \
        char* _p = sm + BBASE + (st) * BBYTES + bofs; \
        uint4 q; \
        q.x = h2u(__floats2half2_rn(bv[0].x, bv[0].y)); \
        q.y = h2u(__floats2half2_rn(bv[0].z, bv[0].w)); \
        q.z = h2u(__floats2half2_rn(bv[1].x, bv[1].y)); \
        q.w = h2u(__floats2half2_rn(bv[1].z, bv[1].w)); \
        *(uint4*)_p = q; \
    } while (0)

    float acc[4][4][4] = {};

    // prologue
    CPA(0); CPCOMMIT();
    CPA(1); CPCOMMIT();
    LDGB(0); STSB(0); LDGB(1);

    const int lr = (l & 7) + ((l >> 3) & 1) * 8;
    const int lc = (l >> 4) * 8;

    for (int it = 0; it < KT; it++) {
        CPWAIT1();                 // A(it) arrived (A(it+1) may be outstanding)
        __syncthreads();           // B(it) visible; stages to be overwritten fully read
        CPA(it + 2); CPCOMMIT();   // A stage (it+2)%3 last read at it-1, behind this sync
        if (it + 1 < KT) STSB((it + 1) % 3);  // B stage last read at it-2, two syncs behind
        LDGB(it + 2);

        if (mi_max > 0) {
            const uint32_t Asb = smb + (uint32_t)((it % 3) * ABYTES);
            const uint32_t Bsb = smb + (uint32_t)(BBASE + (it % 3) * BBYTES);
            #pragma unroll
            for (int ks = 0; ks < 2; ks++) {
                uint32_t a[4][4];
                #pragma unroll
                for (int mi = 0; mi < 4; mi++) {
                    if (mi < mi_max) {
                        uint32_t aadr = Asb + (uint32_t)((wm + mi * 16 + lr) * 80 + (ks * 16 + lc) * 2);
                        LDSM4(a[mi], aadr);
                    }
                }
                uint32_t bA[4], bB[4];
                uint32_t bd = Bsb + (uint32_t)((ks * 16 + lr) * 272);
                LDSM4T(bA, bd + (colA + lc) * 2);
                LDSM4T(bB, bd + (colB + lc) * 2);
                #pragma unroll
                for (int mi = 0; mi < 4; mi++) {
                    if (mi < mi_max) {
                        mma16(acc[mi][0], a[mi], bA + 0);
                        mma16(acc[mi][1], a[mi], bA + 2);
                        mma16(acc[mi][2], a[mi], bB + 0);
                        mma16(acc[mi][3], a[mi], bB + 2);
                    }
                }
            }
        }
    }

    // ---- epilogue ----
    #pragma unroll
    for (int mi = 0; mi < 4; mi++) {
        if (mi >= mi_max) break;
        const int lr0 = wm + mi * 16 + (l >> 2), lr1 = lr0 + 8;
        if (G == 1) {
            // acc[ ][0..1] = gate (cols n0+colA+...), acc[ ][2..3] = up of SAME h cols
            #pragma unroll
            for (int ni = 0; ni < 2; ni++) {
                const int col = n0 + colA + ni * 8 + 2 * (l & 3);
                const float* g = acc[mi][ni];
                const float* u = acc[mi][ni + 2];
                if (lr0 < rows) {
                    float s0 = g[0] / (1.f + __expf(-g[0]));
                    float s1 = g[1] / (1.f + __expf(-g[1]));
                    __half2 h = __floats2half2_rn(u[0] * s0, u[1] * s1);
                    *(uint32_t*)(d_hbuf + (size_t)(row0 + lr0) * ITR + col) = h2u(h);
                }
                if (lr1 < rows) {
                    float s2 = g[2] / (1.f + __expf(-g[2]));
                    float s3 = g[3] / (1.f + __expf(-g[3]));
                    __half2 h = __floats2half2_rn(u[2] * s2, u[3] * s3);
                    *(uint32_t*)(d_hbuf + (size_t)(row0 + lr1) * ITR + col) = h2u(h);
                }
            }
        } else {
            #pragma unroll
            for (int ni = 0; ni < 4; ni++) {
                const int col = n0 + ((ni < 2) ? (colA + ni * 8) : (colB + (ni - 2) * 8))
                                + 2 * (l & 3);
                if (lr0 < rows)
                    *(float2*)&Out[(size_t)(row0 + lr0) * HID + col] =
                        make_float2(acc[mi][ni][0], acc[mi][ni][1]);
                if (lr1 < rows)
                    *(float2*)&Out[(size_t)(row0 + lr1) * HID + col] =
                        make_float2(acc[mi][ni][2], acc[mi][ni][3]);
            }
        }
    }
}

extern "C" void kernel_launch(void* const* d_in, const int* in_sizes, int n_in,
                              void* d_out, int out_size) {
    const float* x    = (const float*)d_in[0];
    const int*   tpe  = (const int*)d_in[1];
    const float* w1w3 = (const float*)d_in[2];
    const float* w2   = (const float*)d_in[3];
    float*       out  = (float*)d_out;

    cudaFuncSetAttribute(moe_gemm<1>, cudaFuncAttributeMaxDynamicSharedMemorySize, SMEMSZ);
    cudaFuncSetAttribute(moe_gemm<2>, cudaFuncAttributeMaxDynamicSharedMemorySize, SMEMSZ);

    prep_kernel<<<TTOK * HID / 2048, 256>>>(x, tpe);
    moe_gemm<1><<<dim3(11, 64), 512, SMEMSZ>>>(w1w3, nullptr);
    moe_gemm<2><<<dim3(8, 64), 512, SMEMSZ>>>(w2, out);
}

// round 15
// speedup vs baseline: 1.0691x; 1.0691x over previous
#include <cuda_runtime.h>
#include <cuda_fp16.h>
#include <cstdint>

#define HID 1024
#define ITR 704
#define NEXP 32
#define TTOK 8192
#define MAXT 64
#define BM 256
#define ABYTES (256*80)             // 20480 per A stage (x3)
#define BBASE  (3*ABYTES)           // 61440
#define BBYTES (32*144)             // 4608 per B stage (x3)
#define SMEMSZ (BBASE + 3*BBYTES)   // 75264
#define G1BLK (64*22)               // 1408
#define G2BLK (64*16)               // 1024

__device__ int d_te[MAXT], d_tr0[MAXT], d_trs[MAXT], d_nt;
__device__ int d_cnt[MAXT];
__device__ unsigned short d_xh[(size_t)TTOK * HID];
__device__ unsigned short d_hbuf[(size_t)TTOK * ITR];

__device__ __forceinline__ uint32_t smem_u32(const void* p) {
    uint32_t a;
    asm("{ .reg .u64 t; cvta.to.shared.u64 t, %1; cvt.u32.u64 %0, t; }" : "=r"(a) : "l"(p));
    return a;
}
__device__ __forceinline__ void cp16(uint32_t dst, const void* src) {
    asm volatile("cp.async.ca.shared.global [%0], [%1], 16;" :: "r"(dst), "l"(src));
}
#define CPCOMMIT() asm volatile("cp.async.commit_group;" ::: "memory")
#define CPWAIT1()  asm volatile("cp.async.wait_group 1;" ::: "memory")

#define LDSM4(r, a) \
    asm volatile("ldmatrix.sync.aligned.m8n8.x4.shared.b16 {%0,%1,%2,%3}, [%4];" \
        : "=r"((r)[0]), "=r"((r)[1]), "=r"((r)[2]), "=r"((r)[3]) : "r"(a))
#define LDSM4T(r, a) \
    asm volatile("ldmatrix.sync.aligned.m8n8.x4.trans.shared.b16 {%0,%1,%2,%3}, [%4];" \
        : "=r"((r)[0]), "=r"((r)[1]), "=r"((r)[2]), "=r"((r)[3]) : "r"(a))

__device__ __forceinline__ void mma16(float* c, const uint32_t* a, const uint32_t* b) {
    asm volatile(
        "mma.sync.aligned.m16n8k16.row.col.f32.f16.f16.f32 "
        "{%0,%1,%2,%3},{%4,%5,%6,%7},{%8,%9},{%0,%1,%2,%3};"
        : "+f"(c[0]), "+f"(c[1]), "+f"(c[2]), "+f"(c[3])
        : "r"(a[0]), "r"(a[1]), "r"(a[2]), "r"(a[3]), "r"(b[0]), "r"(b[1]));
}
__device__ __forceinline__ uint32_t h2u(__half2 h) { return *(uint32_t*)&h; }

__global__ void prep_kernel(const float* __restrict__ x, const int* __restrict__ tpe) {
    if (blockIdx.x == 0) {
        if (threadIdx.x < MAXT) d_cnt[threadIdx.x] = 0;
        if (threadIdx.x < 32) {
            const int e = threadIdx.x;
            const int c = tpe[e];
            const int nte = (c + BM - 1) / BM;
            int off = c, tb = nte;
            #pragma unroll
            for (int d = 1; d < 32; d <<= 1) {
                int o2 = __shfl_up_sync(0xffffffffu, off, d);
                int t2 = __shfl_up_sync(0xffffffffu, tb, d);
                if (e >= d) { off += o2; tb += t2; }
            }
            const int row0 = off - c, t0 = tb - nte;
            for (int i = 0; i < nte; i++) {
                d_te[t0 + i]  = e;
                d_tr0[t0 + i] = row0 + i * BM;
                d_trs[t0 + i] = min(BM, c - i * BM);
            }
            if (e == 31) d_nt = tb;
        }
    }
    const size_t i = ((size_t)blockIdx.x * 256 + threadIdx.x) * 8;
    float4 v0 = *(const float4*)(x + i);
    float4 v1 = *(const float4*)(x + i + 4);
    uint4 q;
    q.x = h2u(__floats2half2_rn(v0.x, v0.y));
    q.y = h2u(__floats2half2_rn(v0.z, v0.w));
    q.z = h2u(__floats2half2_rn(v1.x, v1.y));
    q.w = h2u(__floats2half2_rn(v1.z, v1.w));
    *(uint4*)(d_xh + i) = q;
}

template <int G>
__device__ __forceinline__ void gemm_body(int tile, int nch,
                                          const float* __restrict__ Bin,
                                          float* __restrict__ Out, char* sm) {
    constexpr int KT   = (G == 1) ? 32 : 22;
    constexpr int AST  = (G == 1) ? HID : ITR;          // A row stride (halves)
    constexpr int BROW = (G == 1) ? (2 * ITR) : HID;    // B row stride (floats)
    const int e = d_te[tile], row0 = d_tr0[tile], rows = d_trs[tile];
    const int n0 = nch * ((G == 1) ? 32 : 64);

    const int tid = threadIdx.x, w = tid >> 5, l = tid & 31;
    const int wm = (w >> 1) * 64;        // 4 M bands of 64
    const int wn = (w & 1) * 16;         // 2 N bands of 16
    const uint32_t smb = smem_u32(sm);

    const int mi_max = min(4, max(0, (rows - wm + 15) >> 4));

    const unsigned short* Ah = (G == 1) ? d_xh : d_hbuf;
    const float* Bg = Bin + (size_t)e * ((G == 1) ? (size_t)HID * (2 * ITR)
                                                  : (size_t)ITR * HID);

    // A staging: 4 rows (ar+64i) x 8 halves via cp.async
    const int ar = tid >> 2, ka = (tid & 3) * 8;
    size_t ga[4]; uint32_t ad[4];
    #pragma unroll
    for (int i = 0; i < 4; i++) {
        ga[i] = (size_t)min(row0 + ar + 64 * i, TTOK - 1) * AST + ka;
        ad[i] = (uint32_t)((ar + 64 * i) * 80 + ka * 2);
    }

    // B staging: row kb = tid>>3, 8 cols at nb (2 float4)
    const int kb = tid >> 3, nb = (tid & 7) * 8;
    size_t boff[2];
    #pragma unroll
    for (int j = 0; j < 2; j++) {
        int nloc = nb + 4 * j;
        int col = (G == 1) ? ((nloc < 32) ? (n0 + nloc) : (ITR + n0 + nloc - 32))
                           : (n0 + nloc);
        boff[j] = (size_t)kb * BROW + col;
    }
    const int bofs = kb * 144 + nb * 2;

    #define CPA(it) do { if ((it) < KT) { \
        const uint32_t _d = smb + (uint32_t)((((it) % 3)) * ABYTES); \
        const size_t _ko = (size_t)(it) * 32; \
        cp16(_d + ad[0], Ah + ga[0] + _ko); \
        cp16(_d + ad[1], Ah + ga[1] + _ko); \
        cp16(_d + ad[2], Ah + ga[2] + _ko); \
        cp16(_d + ad[3], Ah + ga[3] + _ko); } } while (0)

    float4 bv[2];
    #define LDGB(it) do { if ((it) < KT) { \
        bv[0] = *(const float4*)(Bg + boff[0] + (size_t)(it) * 32 * BROW); \
        bv[1] = *(const float4*)(Bg + boff[1] + (size_t)(it) * 32 * BROW); } } while (0)

    #define STSB(st) do { \
        char* _p = sm + BBASE + (st) * BBYTES + bofs; \
        uint4 q; \
        q.x = h2u(__floats2half2_rn(bv[0].x, bv[0].y)); \
        q.y = h2u(__floats2half2_rn(bv[0].z, bv[0].w)); \
        q.z = h2u(__floats2half2_rn(bv[1].x, bv[1].y)); \
        q.w = h2u(__floats2half2_rn(bv[1].z, bv[1].w)); \
        *(uint4*)_p = q; \
    } while (0)

    float acc[4][4][4] = {};

    // prologue
    CPA(0); CPCOMMIT();
    CPA(1); CPCOMMIT();
    LDGB(0); STSB(0); LDGB(1);

    const int lr = (l & 7) + ((l >> 3) & 1) * 8;
    const int lc = (l >> 4) * 8;

    for (int it = 0; it < KT; it++) {
        CPWAIT1();                 // A(it) arrived (A(it+1) may be outstanding)
        __syncthreads();           // B(it) visible; stages to be overwritten fully read
        CPA(it + 2); CPCOMMIT();   // A stage (it+2)%3 last read at it-1, behind this sync
        if (it + 1 < KT) STSB((it + 1) % 3);  // B stage last read at it-2, two syncs behind
        LDGB(it + 2);

        if (mi_max > 0) {
            const uint32_t Asb = smb + (uint32_t)((it % 3) * ABYTES);
            const uint32_t Bsb = smb + (uint32_t)(BBASE + (it % 3) * BBYTES);
            #pragma unroll
            for (int ks = 0; ks < 2; ks++) {
                uint32_t a[4][4];
                #pragma unroll
                for (int mi = 0; mi < 4; mi++) {
                    if (mi < mi_max) {
                        uint32_t aadr = Asb + (uint32_t)((wm + mi * 16 + lr) * 80 + (ks * 16 + lc) * 2);
                        LDSM4(a[mi], aadr);
                    }
                }
                uint32_t bA[4], bB[4];
                uint32_t bd = Bsb + (uint32_t)((ks * 16 + lr) * 144);
                LDSM4T(bA, bd + (wn + lc) * 2);
                LDSM4T(bB, bd + (32 + wn + lc) * 2);
                #pragma unroll
                for (int mi = 0; mi < 4; mi++) {
                    if (mi < mi_max) {
                        mma16(acc[mi][0], a[mi], bA + 0);
                        mma16(acc[mi][1], a[mi], bA + 2);
                        mma16(acc[mi][2], a[mi], bB + 0);
                        mma16(acc[mi][3], a[mi], bB + 2);
                    }
                }
            }
        }
    }

    // ---- epilogue ----
    #pragma unroll
    for (int mi = 0; mi < 4; mi++) {
        if (mi >= mi_max) break;
        const int lr0 = wm + mi * 16 + (l >> 2), lr1 = lr0 + 8;
        if (G == 1) {
            #pragma unroll
            for (int ni = 0; ni < 2; ni++) {
                const int col = n0 + wn + ni * 8 + 2 * (l & 3);
                const float* g = acc[mi][ni];
                const float* u = acc[mi][ni + 2];
                if (lr0 < rows) {
                    float s0 = g[0] / (1.f + __expf(-g[0]));
                    float s1 = g[1] / (1.f + __expf(-g[1]));
                    __half2 h = __floats2half2_rn(u[0] * s0, u[1] * s1);
                    *(uint32_t*)(d_hbuf + (size_t)(row0 + lr0) * ITR + col) = h2u(h);
                }
                if (lr1 < rows) {
                    float s2 = g[2] / (1.f + __expf(-g[2]));
                    float s3 = g[3] / (1.f + __expf(-g[3]));
                    __half2 h = __floats2half2_rn(u[2] * s2, u[3] * s3);
                    *(uint32_t*)(d_hbuf + (size_t)(row0 + lr1) * ITR + col) = h2u(h);
                }
            }
        } else {
            #pragma unroll
            for (int ni = 0; ni < 4; ni++) {
                const int col = n0 + ((ni < 2) ? (wn + ni * 8) : (32 + wn + (ni - 2) * 8))
                                + 2 * (l & 3);
                if (lr0 < rows)
                    *(float2*)&Out[(size_t)(row0 + lr0) * HID + col] =
                        make_float2(acc[mi][ni][0], acc[mi][ni][1]);
                if (lr1 < rows)
                    *(float2*)&Out[(size_t)(row0 + lr1) * HID + col] =
                        make_float2(acc[mi][ni][2], acc[mi][ni][3]);
            }
        }
    }
    #undef CPA
    #undef LDGB
    #undef STSB
}

__global__ __launch_bounds__(256, 2) void moe_fused(const float* __restrict__ w1w3,
                                                    const float* __restrict__ w2,
                                                    float* __restrict__ out) {
    extern __shared__ __align__(16) char sm[];
    const int bid = blockIdx.x;
    if (bid < G1BLK) {
        const int tile = bid / 22, nch = bid - tile * 22;
        if (tile >= d_nt) return;
        gemm_body<1>(tile, nch, w1w3, nullptr, sm);
        __syncthreads();            // all h stores of this block issued
        __threadfence();            // release: h visible before count bump
        if (threadIdx.x == 0) atomicAdd(&d_cnt[tile], 1);
    } else {
        const int b2 = bid - G1BLK;
        const int tile = b2 >> 4, nch = b2 & 15;
        if (tile >= d_nt) return;
        if (threadIdx.x == 0) {
            while (atomicAdd(&d_cnt[tile], 0) < 22) __nanosleep(128);
            __threadfence();        // acquire: h reads ordered after flag
        }
        __syncthreads();            // propagate acquire to all threads
        gemm_body<2>(tile, nch, w2, out, sm);
    }
}

extern "C" void kernel_launch(void* const* d_in, const int* in_sizes, int n_in,
                              void* d_out, int out_size) {
    const float* x    = (const float*)d_in[0];
    const int*   tpe  = (const int*)d_in[1];
    const float* w1w3 = (const float*)d_in[2];
    const float* w2   = (const float*)d_in[3];
    float*       out  = (float*)d_out;

    cudaFuncSetAttribute(moe_fused, cudaFuncAttributeMaxDynamicSharedMemorySize, SMEMSZ);

    prep_kernel<<<TTOK * HID / 2048, 256>>>(x, tpe);
    moe_fused<<<G1BLK + G2BLK, 256, SMEMSZ>>>(w1w3, w2, out);
}